// round 7
// baseline (speedup 1.0000x reference)
#include <cuda_runtime.h>
#include <cuda_fp16.h>
#include <cstdint>

#define TOKENS 4096
#define DIN    1024
#define DHID   4096
#define DOUT   1024
#define NEXP   8

// ---------------- device scratch ----------------
__device__ __half g_xh [TOKENS * DIN];                          // x fp16 [M][K]
__device__ __half g_B1t[(NEXP + 1) * (size_t)DHID * DIN];       // [e][n][k] K-major (e=8 -> Wg1)
__device__ __half g_W2t[(size_t)DOUT * NEXP * DHID];            // [n][k'] k'=e*4096+h, ld=32768
__device__ __half g_H  [(NEXP + 1) * (size_t)TOKENS * DHID];    // H[e][b][h]; slot 8 = gating hidden
__device__ float  g_gate[TOKENS * NEXP];
__device__ float  g_gb2 [TOKENS * DOUT];                        // gate @ b2

// ---------------- PTX helpers ----------------
__device__ __forceinline__ void cp_async16(uint32_t dst, const void* src) {
    asm volatile("cp.async.cg.shared.global [%0], [%1], 16;\n" :: "r"(dst), "l"(src));
}
__device__ __forceinline__ void cp_commit() {
    asm volatile("cp.async.commit_group;\n" ::: "memory");
}
__device__ __forceinline__ void cp_wait1() {
    asm volatile("cp.async.wait_group 1;\n" ::: "memory");
}
__device__ __forceinline__ void ldsm_x4(uint32_t* r, uint32_t addr) {
    asm volatile("ldmatrix.sync.aligned.m8n8.x4.shared.b16 {%0,%1,%2,%3}, [%4];\n"
                 : "=r"(r[0]), "=r"(r[1]), "=r"(r[2]), "=r"(r[3]) : "r"(addr));
}
__device__ __forceinline__ void mma16816(float* c, const uint32_t* a, uint32_t b0, uint32_t b1) {
    asm volatile("mma.sync.aligned.m16n8k16.row.col.f32.f16.f16.f32 "
                 "{%0,%1,%2,%3},{%4,%5,%6,%7},{%8,%9},{%0,%1,%2,%3};\n"
                 : "+f"(c[0]), "+f"(c[1]), "+f"(c[2]), "+f"(c[3])
                 : "r"(a[0]), "r"(a[1]), "r"(a[2]), "r"(a[3]), "r"(b0), "r"(b1));
}
__device__ __forceinline__ uint32_t swz(uint32_t off) {   // SW128: XOR 16B-chunk by row%8
    return off ^ ((off >> 3) & 0x70);
}

// ---------------- converts ----------------
__global__ void cvt_f32_f16(const float* __restrict__ src, __half* __restrict__ dst, int n) {
    int i = (blockIdx.x * blockDim.x + threadIdx.x) * 4;
    if (i >= n) return;
    float4 v = *(const float4*)(src + i);
    *(__half2*)(dst + i)     = __floats2half2_rn(v.x, v.y);
    *(__half2*)(dst + i + 2) = __floats2half2_rn(v.z, v.w);
}

// transpose+convert: out[z*outSlab + c*ldo + r] = in[z*inSlab + r*C + c]
__global__ void __launch_bounds__(256) transpose_cvt(
    const float* __restrict__ in, __half* __restrict__ out,
    int R, int C, long long inSlab, long long outSlab, int ldo)
{
    __shared__ float t[32][33];
    const float* src = in + (long long)blockIdx.z * inSlab;
    __half* dst = out + (long long)blockIdx.z * outSlab;
    int c0 = blockIdx.x * 32, r0 = blockIdx.y * 32;
    int tx = threadIdx.x & 31, ty = threadIdx.x >> 5;   // 32x8
#pragma unroll
    for (int j = ty; j < 32; j += 8)
        t[j][tx] = src[(long long)(r0 + j) * C + c0 + tx];
    __syncthreads();
#pragma unroll
    for (int j = ty; j < 32; j += 8)
        dst[(long long)(c0 + j) * ldo + r0 + tx] = __float2half_rn(t[tx][j]);
}

// ---------------- gating softmax ----------------
__global__ void __launch_bounds__(256) gate_kernel(
    const __half* __restrict__ Hg, const float* __restrict__ Wg2,
    const float* __restrict__ bg2, float* __restrict__ gate)
{
    extern __shared__ float sW[];   // [8][4096] transposed
    const int tid = threadIdx.x;
    for (int i = tid; i < DHID * NEXP; i += 256) {
        int k = i >> 3, j = i & 7;
        sW[j * DHID + k] = Wg2[i];
    }
    __syncthreads();
    const int warp = tid >> 5, lane = tid & 31;
    const int row = blockIdx.x * 8 + warp;
    const __half* h = Hg + (long long)row * DHID;
    float a[NEXP];
#pragma unroll
    for (int j = 0; j < NEXP; j++) a[j] = 0.f;
    for (int k = lane; k < DHID; k += 32) {
        float x = __half2float(h[k]);
#pragma unroll
        for (int j = 0; j < NEXP; j++) a[j] += x * sW[j * DHID + k];
    }
#pragma unroll
    for (int j = 0; j < NEXP; j++)
#pragma unroll
        for (int o = 16; o > 0; o >>= 1) a[j] += __shfl_xor_sync(0xffffffffu, a[j], o);
    float m = -1e30f;
#pragma unroll
    for (int j = 0; j < NEXP; j++) { a[j] += bg2[j]; m = fmaxf(m, a[j]); }
    float ex[NEXP], s = 0.f;
#pragma unroll
    for (int j = 0; j < NEXP; j++) { ex[j] = expf(a[j] - m); s += ex[j]; }
    if (lane < NEXP) gate[row * NEXP + lane] = ex[lane] / s;
}

// gb2[b][o] = sum_j gate[b][j] * b2[j][o]
__global__ void __launch_bounds__(256) gb2_kernel(
    const float* __restrict__ gate, const float* __restrict__ b2, float* __restrict__ gb2)
{
    int b = blockIdx.x;
    float g[NEXP];
#pragma unroll
    for (int j = 0; j < NEXP; j++) g[j] = gate[b * NEXP + j];
    for (int o = threadIdx.x; o < DOUT; o += 256) {
        float s = 0.f;
#pragma unroll
        for (int j = 0; j < NEXP; j++) s += g[j] * b2[j * DOUT + o];
        gb2[b * DOUT + o] = s;
    }
}

// ---------------- HMMA GEMM, 128x256x64 CTA tile, 64x64 warp tile ----------------
// A: [M][K] row-major fp16.  B: [N][K] row-major fp16 (K-major).  Both K%64==0.
// MODE 0: C = relu(A@B^T + bias)            -> fp16
// MODE 1: C = gate[b,e]*relu(A@B^T + bias)  -> fp16
// MODE 2: C = A@B^T + gb2[b,:]              -> fp32  (K = 32768, A blocked by expert slab)
constexpr int BM = 128, BN = 256, BK = 64, STAGES = 3;
constexpr int A_BYTES = BM * 128;               // 16 KB (64 halves = 128B rows, SW128)
constexpr int B_BYTES = BN * 128;               // 32 KB
constexpr int STAGE_BYTES = A_BYTES + B_BYTES;  // 48 KB
constexpr int GEMM_SMEM = STAGES * STAGE_BYTES; // 147456 B

template <int MODE>
__global__ void __launch_bounds__(256, 1) moe_mma(
    const __half* __restrict__ A, long long aSlab, int lda,
    const __half* __restrict__ Bb, long long bStride, int ldb,
    const float* __restrict__ biasBase, long long biasStride,
    const float* __restrict__ gate, const float* __restrict__ gb2,
    void* __restrict__ Cb, long long cStride, int ldc, int K)
{
    extern __shared__ char smem[];
    const uint32_t sbase = (uint32_t)__cvta_generic_to_shared(smem);
    const int tid = threadIdx.x, lane = tid & 31, warp = tid >> 5;
    const int wm = warp >> 2, wn = warp & 3;       // 2x4 warp grid
    const int bm0 = blockIdx.y * BM, bn0 = blockIdx.x * BN, e = blockIdx.z;

    const __half* Bm = Bb + (long long)e * bStride;
    const int KT = K / BK;

    auto fill = [&](int kt, int buf) {
        const int k0 = kt * BK;
        const __half* aS = A + (long long)(k0 >> 12) * aSlab + (k0 & 4095);
        const __half* bS = Bm + k0;
        const uint32_t base = sbase + buf * STAGE_BYTES;
#pragma unroll
        for (int i = 0; i < 12; i++) {
            int idx = tid + i * 256;
            if (idx < 1024) {                      // A: 128 rows x 8 chunks
                int r = idx >> 3, c = idx & 7;
                cp_async16(base + swz((uint32_t)(r * 128 + c * 16)),
                           aS + (long long)(bm0 + r) * lda + c * 8);
            } else {                               // B: 256 rows x 8 chunks
                int j = idx - 1024;
                int r = j >> 3, c = j & 7;
                cp_async16(base + A_BYTES + swz((uint32_t)(r * 128 + c * 16)),
                           bS + (long long)(bn0 + r) * ldb + c * 8);
            }
        }
        cp_commit();
    };

    float acc[4][8][4];
#pragma unroll
    for (int a = 0; a < 4; a++)
#pragma unroll
        for (int b = 0; b < 8; b++)
#pragma unroll
            for (int c = 0; c < 4; c++) acc[a][b][c] = 0.f;

    fill(0, 0);
    fill(1, 1);

    const int lr  = lane & 15;            // row within 16
    const int lcb = (lane >> 4) << 4;     // byte col within 32B (0 or 16)

    for (int kt = 0; kt < KT; kt++) {
        cp_wait1();
        __syncthreads();
        const int nt = kt + 2;
        if (nt < KT) fill(nt, nt % STAGES);
        else         cp_commit();          // empty group keeps wait accounting aligned

        const uint32_t aB = sbase + (kt % STAGES) * STAGE_BYTES;
        const uint32_t bB = aB + A_BYTES;
#pragma unroll
        for (int ks = 0; ks < BK / 16; ks++) {
            uint32_t af[4][4];
#pragma unroll
            for (int mb = 0; mb < 4; mb++)
                ldsm_x4(af[mb], aB + swz((uint32_t)((wm * 64 + mb * 16 + lr) * 128 + ks * 32 + lcb)));
#pragma unroll
            for (int nb = 0; nb < 4; nb++) {
                uint32_t bf[4];
                ldsm_x4(bf, bB + swz((uint32_t)((wn * 64 + nb * 16 + lr) * 128 + ks * 32 + lcb)));
#pragma unroll
                for (int mb = 0; mb < 4; mb++) {
                    mma16816(acc[mb][2 * nb],     af[mb], bf[0], bf[2]);
                    mma16816(acc[mb][2 * nb + 1], af[mb], bf[1], bf[3]);
                }
            }
        }
        __syncthreads();
    }

    // -------- epilogue --------
    const int g  = lane >> 2;
    const int tg = lane & 3;

    if constexpr (MODE == 0 || MODE == 1) {
        __half* C = (__half*)Cb + (long long)e * cStride;
        const float* bias = biasBase + (long long)e * biasStride;
#pragma unroll
        for (int mb = 0; mb < 4; mb++)
#pragma unroll
            for (int i = 0; i < 2; i++) {
                const int row = bm0 + wm * 64 + mb * 16 + g + i * 8;
                float gv = 1.f;
                if constexpr (MODE == 1) gv = gate[row * NEXP + e];
#pragma unroll
                for (int nb = 0; nb < 8; nb++) {
                    const int col = bn0 + wn * 64 + nb * 8 + tg * 2;
                    float v0 = fmaxf(acc[mb][nb][2 * i + 0] + bias[col],     0.f) * gv;
                    float v1 = fmaxf(acc[mb][nb][2 * i + 1] + bias[col + 1], 0.f) * gv;
                    *(__half2*)(C + (long long)row * ldc + col) = __floats2half2_rn(v0, v1);
                }
            }
    } else {
        float* C = (float*)Cb;
#pragma unroll
        for (int mb = 0; mb < 4; mb++)
#pragma unroll
            for (int i = 0; i < 2; i++) {
                const int row = bm0 + wm * 64 + mb * 16 + g + i * 8;
                const float* gp = gb2 + (long long)row * DOUT;
#pragma unroll
                for (int nb = 0; nb < 8; nb++) {
                    const int col = bn0 + wn * 64 + nb * 8 + tg * 2;
                    float2 o;
                    o.x = acc[mb][nb][2 * i + 0] + gp[col];
                    o.y = acc[mb][nb][2 * i + 1] + gp[col + 1];
                    *(float2*)(C + (long long)row * ldc + col) = o;
                }
            }
    }
}

// ---------------- launch ----------------
extern "C" void kernel_launch(void* const* d_in, const int* in_sizes, int n_in,
                              void* d_out, int out_size)
{
    const float* x   = (const float*)d_in[0];
    const float* W1  = (const float*)d_in[1];
    const float* b1  = (const float*)d_in[2];
    const float* W2  = (const float*)d_in[3];
    const float* b2  = (const float*)d_in[4];
    const float* Wg1 = (const float*)d_in[5];
    const float* bg1 = (const float*)d_in[6];
    const float* Wg2 = (const float*)d_in[7];
    const float* bg2 = (const float*)d_in[8];

    __half *xh, *B1t, *W2t, *H;
    float *gate, *gb2;
    cudaGetSymbolAddress((void**)&xh,   g_xh);
    cudaGetSymbolAddress((void**)&B1t,  g_B1t);
    cudaGetSymbolAddress((void**)&W2t,  g_W2t);
    cudaGetSymbolAddress((void**)&H,    g_H);
    cudaGetSymbolAddress((void**)&gate, g_gate);
    cudaGetSymbolAddress((void**)&gb2,  g_gb2);

    cudaFuncSetAttribute(moe_mma<0>, cudaFuncAttributeMaxDynamicSharedMemorySize, GEMM_SMEM);
    cudaFuncSetAttribute(moe_mma<1>, cudaFuncAttributeMaxDynamicSharedMemorySize, GEMM_SMEM);
    cudaFuncSetAttribute(moe_mma<2>, cudaFuncAttributeMaxDynamicSharedMemorySize, GEMM_SMEM);
    cudaFuncSetAttribute(gate_kernel, cudaFuncAttributeMaxDynamicSharedMemorySize, DHID * NEXP * 4);

    // converts + weight transposes to K-major fp16
    cvt_f32_f16<<<TOKENS * DIN / 1024, 256>>>(x, xh, TOKENS * DIN);
    transpose_cvt<<<dim3(DHID / 32, DIN / 32, NEXP), 256>>>(
        W1, B1t, DIN, DHID, (long long)DIN * DHID, (long long)DHID * DIN, DIN);
    transpose_cvt<<<dim3(DHID / 32, DIN / 32, 1), 256>>>(
        Wg1, B1t + (long long)NEXP * DHID * DIN, DIN, DHID, 0, 0, DIN);
    transpose_cvt<<<dim3(DOUT / 32, DHID / 32, NEXP), 256>>>(
        W2, W2t, DHID, DOUT, (long long)DHID * DOUT, (long long)DHID, NEXP * DHID);

    // 1) gating hidden: Hg = relu(x @ Wg1^T + bg1)   (slot 8)
    moe_mma<0><<<dim3(DHID / BN, TOKENS / BM, 1), 256, GEMM_SMEM>>>(
        xh, 0, DIN,
        B1t + (long long)NEXP * DHID * DIN, 0, DIN,
        bg1, 0, nullptr, nullptr,
        H + (long long)NEXP * TOKENS * DHID, 0, DHID, DIN);

    // 2) gates + gate@b2
    gate_kernel<<<TOKENS / 8, 256, DHID * NEXP * 4>>>(
        H + (long long)NEXP * TOKENS * DHID, Wg2, bg2, gate);
    gb2_kernel<<<TOKENS, 256>>>(gate, b2, gb2);

    // 3) expert layer-1 (batched over e): H[e] = gate[b,e]*relu(x @ W1[e]^T + b1[e])
    moe_mma<1><<<dim3(DHID / BN, TOKENS / BM, NEXP), 256, GEMM_SMEM>>>(
        xh, 0, DIN,
        B1t, (long long)DHID * DIN, DIN,
        b1, DHID, gate, nullptr,
        H, (long long)TOKENS * DHID, DHID, DIN);

    // 4) layer-2: out = Hflat @ W2t^T + gate@b2   (K = 32768)
    moe_mma<2><<<dim3(DOUT / BN, TOKENS / BM, 1), 256, GEMM_SMEM>>>(
        H, (long long)TOKENS * DHID, DHID,
        W2t, 0, NEXP * DHID,
        nullptr, 0, nullptr, gb2,
        d_out, 0, DOUT, NEXP * DHID);
}

// round 8
// speedup vs baseline: 1.1692x; 1.1692x over previous
#include <cuda_runtime.h>
#include <cuda_fp16.h>
#include <cstdint>

#define TOKENS 4096
#define DIN    1024
#define DHID   4096
#define DOUT   1024
#define NEXP   8

// ---------------- device scratch ----------------
__device__ __half g_xh [TOKENS * DIN];                          // x fp16 [M][K]
__device__ __half g_B1 [(NEXP + 1) * (size_t)DIN * DHID];       // W1 [e][K][N] + Wg1 (e=8), fp16
__device__ __half g_W2h[(size_t)NEXP * DHID * DOUT];            // W2 flat [32768][1024] fp16
__device__ __half g_H  [(NEXP + 1) * (size_t)TOKENS * DHID];    // H[e][b][h]; slot 8 = gating hidden
__device__ float  g_gate[TOKENS * NEXP];
__device__ float  g_gb2 [TOKENS * DOUT];                        // gate @ b2
__device__ float  g_part[NEXP * (size_t)TOKENS * DOUT];         // split-K partials (128 MB)

// ---------------- PTX helpers ----------------
__device__ __forceinline__ void cp_async16(unsigned dst, const void* src) {
    asm volatile("cp.async.cg.shared.global [%0], [%1], 16;\n" :: "r"(dst), "l"(src));
}
__device__ __forceinline__ void cp_commit() {
    asm volatile("cp.async.commit_group;\n" ::: "memory");
}
__device__ __forceinline__ void cp_wait1() {
    asm volatile("cp.async.wait_group 1;\n" ::: "memory");
}
__device__ __forceinline__ void ldsm_x4(uint32_t* r, unsigned addr) {
    asm volatile("ldmatrix.sync.aligned.m8n8.x4.shared.b16 {%0,%1,%2,%3}, [%4];\n"
                 : "=r"(r[0]), "=r"(r[1]), "=r"(r[2]), "=r"(r[3]) : "r"(addr));
}
__device__ __forceinline__ void ldsm_x4_t(uint32_t* r, unsigned addr) {
    asm volatile("ldmatrix.sync.aligned.m8n8.x4.trans.shared.b16 {%0,%1,%2,%3}, [%4];\n"
                 : "=r"(r[0]), "=r"(r[1]), "=r"(r[2]), "=r"(r[3]) : "r"(addr));
}
__device__ __forceinline__ void mma16816(float* c, const uint32_t* a, uint32_t b0, uint32_t b1) {
    asm volatile("mma.sync.aligned.m16n8k16.row.col.f32.f16.f16.f32 "
                 "{%0,%1,%2,%3},{%4,%5,%6,%7},{%8,%9},{%0,%1,%2,%3};\n"
                 : "+f"(c[0]), "+f"(c[1]), "+f"(c[2]), "+f"(c[3])
                 : "r"(a[0]), "r"(a[1]), "r"(a[2]), "r"(a[3]), "r"(b0), "r"(b1));
}

// ---------------- fp32 -> fp16 convert ----------------
__global__ void cvt_f32_f16(const float* __restrict__ src, __half* __restrict__ dst, int n) {
    int i = (blockIdx.x * blockDim.x + threadIdx.x) * 4;
    if (i >= n) return;
    float4 v = *(const float4*)(src + i);
    *(__half2*)(dst + i)     = __floats2half2_rn(v.x, v.y);
    *(__half2*)(dst + i + 2) = __floats2half2_rn(v.z, v.w);
}

// ---------------- gating softmax ----------------
__global__ void __launch_bounds__(256) gate_kernel(
    const __half* __restrict__ Hg, const float* __restrict__ Wg2,
    const float* __restrict__ bg2, float* __restrict__ gate)
{
    extern __shared__ float sW[];   // [8][4096] transposed
    const int tid = threadIdx.x;
    for (int i = tid; i < DHID * NEXP; i += 256) {
        int k = i >> 3, j = i & 7;
        sW[j * DHID + k] = Wg2[i];
    }
    __syncthreads();
    const int warp = tid >> 5, lane = tid & 31;
    const int row = blockIdx.x * 8 + warp;
    const __half2* h2 = (const __half2*)(Hg + (long long)row * DHID);
    float a[NEXP];
#pragma unroll
    for (int j = 0; j < NEXP; j++) a[j] = 0.f;
    for (int k2 = lane; k2 < DHID / 2; k2 += 32) {
        float2 xv = __half22float2(h2[k2]);
#pragma unroll
        for (int j = 0; j < NEXP; j++)
            a[j] += xv.x * sW[j * DHID + 2 * k2] + xv.y * sW[j * DHID + 2 * k2 + 1];
    }
#pragma unroll
    for (int j = 0; j < NEXP; j++)
#pragma unroll
        for (int o = 16; o > 0; o >>= 1) a[j] += __shfl_xor_sync(0xffffffffu, a[j], o);
    float m = -1e30f;
#pragma unroll
    for (int j = 0; j < NEXP; j++) { a[j] += bg2[j]; m = fmaxf(m, a[j]); }
    float ex[NEXP], s = 0.f;
#pragma unroll
    for (int j = 0; j < NEXP; j++) { ex[j] = expf(a[j] - m); s += ex[j]; }
    if (lane < NEXP) gate[row * NEXP + lane] = ex[lane] / s;
}

// gb2[b][o] = sum_j gate[b][j] * b2[j][o]
__global__ void __launch_bounds__(256) gb2_kernel(
    const float* __restrict__ gate, const float* __restrict__ b2, float* __restrict__ gb2)
{
    int b = blockIdx.x;
    float g[NEXP];
#pragma unroll
    for (int j = 0; j < NEXP; j++) g[j] = gate[b * NEXP + j];
    for (int o = threadIdx.x; o < DOUT; o += 256) {
        float s = 0.f;
#pragma unroll
        for (int j = 0; j < NEXP; j++) s += g[j] * b2[j * DOUT + o];
        gb2[b * DOUT + o] = s;
    }
}

// out = gb2 + sum_e part[e]
__global__ void __launch_bounds__(256) reduce_kernel(
    const float* __restrict__ part, const float* __restrict__ gb2, float* __restrict__ out)
{
    const long long i = ((long long)blockIdx.x * 256 + threadIdx.x) * 4;
    float4 s = *(const float4*)(gb2 + i);
#pragma unroll
    for (int e = 0; e < NEXP; e++) {
        float4 p = *(const float4*)(part + (long long)e * TOKENS * DOUT + i);
        s.x += p.x; s.y += p.y; s.z += p.z; s.w += p.w;
    }
    *(float4*)(out + i) = s;
}

// ---------------- fused fp16 GEMM (R1 core, single sync, split-K MODE2) ----------------
// A: [M][K] row-major fp16.  B: [K][N] row-major fp16.
// MODE 0: C = relu(A@B + bias)                -> fp16   (gating layer-1)
// MODE 1: C = gate[b,e]*relu(A@B + bias_e)    -> fp16   (expert layer-1, z=e)
// MODE 2: C = A_e@B_e                         -> fp32   (layer-2 partial, z=e, K=4096)
constexpr int BM = 128, BN = 128, BK = 64, STAGES = 3;
constexpr int ASTR = BK + 8;          // 72 halves
constexpr int BSTR = BN + 8;          // 136 halves
constexpr int A_TILE = BM * ASTR;     // halves
constexpr int B_TILE = BK * BSTR;
constexpr int SMEM_BYTES = STAGES * (A_TILE + B_TILE) * 2;   // 107,520 B

template <int MODE>
__global__ void __launch_bounds__(256) moe_gemm(
    const __half* __restrict__ Abase, long long aSlab, int lda,
    const __half* __restrict__ Bbase, long long bStride, int ldb,
    const float* __restrict__ biasBase, long long biasStride,
    const float* __restrict__ gate,
    void* __restrict__ Cbase, long long cStride, int ldc,
    int K)
{
    extern __shared__ __half sm_[];
    __half* As = sm_;
    __half* Bs = sm_ + STAGES * A_TILE;

    const int tid  = threadIdx.x;
    const int lane = tid & 31;
    const int warp = tid >> 5;
    const int wm = warp >> 1, wn = warp & 1;   // 4x2 warp grid, warp tile 32x64
    const int bm0 = blockIdx.y * BM;
    const int bn0 = blockIdx.x * BN;
    const int e   = blockIdx.z;

    const __half* Amat = Abase + (MODE == 2 ? (long long)e * aSlab : 0LL);
    const __half* Bmat = Bbase + (long long)e * bStride;

    const unsigned sA0 = (unsigned)__cvta_generic_to_shared(As);
    const unsigned sB0 = (unsigned)__cvta_generic_to_shared(Bs);

    float acc[2][8][4];
#pragma unroll
    for (int a = 0; a < 2; a++)
#pragma unroll
        for (int b = 0; b < 8; b++)
#pragma unroll
            for (int c = 0; c < 4; c++) acc[a][b][c] = 0.f;

    const int KT = K / BK;

    auto load_tile = [&](int kt, int buf) {
        const int k0 = kt * BK;
        const __half* aSrc = Amat + k0;
        const __half* bSrc = Bmat + (long long)k0 * ldb + bn0;
        const unsigned da = sA0 + buf * (A_TILE * 2);
        const unsigned db = sB0 + buf * (B_TILE * 2);
#pragma unroll
        for (int i = 0; i < 4; i++) {
            int c = tid + i * 256;
            int r = c >> 3, c8 = (c & 7) << 3;
            cp_async16(da + (unsigned)(r * ASTR + c8) * 2,
                       aSrc + (long long)(bm0 + r) * lda + c8);
        }
#pragma unroll
        for (int i = 0; i < 4; i++) {
            int c = tid + i * 256;
            int r = c >> 4, c16 = (c & 15) << 3;
            cp_async16(db + (unsigned)(r * BSTR + c16) * 2,
                       bSrc + (long long)r * ldb + c16);
        }
        cp_commit();
    };

    load_tile(0, 0);
    load_tile(1, 1);

    const int lr = lane & 15;
    const int lc = (lane >> 4) << 3;

    for (int kt = 0; kt < KT; kt++) {
        cp_wait1();
        __syncthreads();
        const int nt = kt + 2;
        if (nt < KT) load_tile(nt, nt % STAGES);
        else         cp_commit();     // empty group keeps wait accounting aligned

        const int buf = kt % STAGES;
        const unsigned aB = sA0 + buf * (A_TILE * 2);
        const unsigned bB = sB0 + buf * (B_TILE * 2);
#pragma unroll
        for (int ks = 0; ks < BK / 16; ks++) {
            uint32_t af[2][4];
#pragma unroll
            for (int mb = 0; mb < 2; mb++)
                ldsm_x4(af[mb], aB + (unsigned)((wm * 32 + mb * 16 + lr) * ASTR + ks * 16 + lc) * 2);
            uint32_t bf[4][4];
#pragma unroll
            for (int nb = 0; nb < 4; nb++)
                ldsm_x4_t(bf[nb], bB + (unsigned)((ks * 16 + lr) * BSTR + wn * 64 + nb * 16 + lc) * 2);
#pragma unroll
            for (int mb = 0; mb < 2; mb++)
#pragma unroll
                for (int nb = 0; nb < 4; nb++) {
                    mma16816(acc[mb][2 * nb],     af[mb], bf[nb][0], bf[nb][1]);
                    mma16816(acc[mb][2 * nb + 1], af[mb], bf[nb][2], bf[nb][3]);
                }
        }
    }

    // -------- epilogue --------
    const int g  = lane >> 2;
    const int tg = lane & 3;

    if constexpr (MODE == 0 || MODE == 1) {
        __half* C = (__half*)Cbase + (long long)e * cStride;
        const float* bias = biasBase + (long long)e * biasStride;
#pragma unroll
        for (int mb = 0; mb < 2; mb++)
#pragma unroll
            for (int i = 0; i < 2; i++) {
                const int row = bm0 + wm * 32 + mb * 16 + g + i * 8;
                float gv = 1.f;
                if constexpr (MODE == 1) gv = gate[row * NEXP + e];
#pragma unroll
                for (int nb = 0; nb < 8; nb++) {
                    const int col = bn0 + wn * 64 + nb * 8 + tg * 2;
                    float v0 = fmaxf(acc[mb][nb][2 * i + 0] + bias[col],     0.f) * gv;
                    float v1 = fmaxf(acc[mb][nb][2 * i + 1] + bias[col + 1], 0.f) * gv;
                    *(__half2*)(C + (long long)row * ldc + col) = __floats2half2_rn(v0, v1);
                }
            }
    } else {
        float* C = (float*)Cbase + (long long)e * cStride;
#pragma unroll
        for (int mb = 0; mb < 2; mb++)
#pragma unroll
            for (int i = 0; i < 2; i++) {
                const int row = bm0 + wm * 32 + mb * 16 + g + i * 8;
#pragma unroll
                for (int nb = 0; nb < 8; nb++) {
                    const int col = bn0 + wn * 64 + nb * 8 + tg * 2;
                    float2 o;
                    o.x = acc[mb][nb][2 * i + 0];
                    o.y = acc[mb][nb][2 * i + 1];
                    *(float2*)(C + (long long)row * ldc + col) = o;
                }
            }
    }
}

// ---------------- launch ----------------
extern "C" void kernel_launch(void* const* d_in, const int* in_sizes, int n_in,
                              void* d_out, int out_size)
{
    const float* x   = (const float*)d_in[0];
    const float* W1  = (const float*)d_in[1];
    const float* b1  = (const float*)d_in[2];
    const float* W2  = (const float*)d_in[3];
    const float* b2  = (const float*)d_in[4];
    const float* Wg1 = (const float*)d_in[5];
    const float* bg1 = (const float*)d_in[6];
    const float* Wg2 = (const float*)d_in[7];
    const float* bg2 = (const float*)d_in[8];

    __half *xh, *B1, *W2h, *H;
    float *gate, *gb2, *part;
    cudaGetSymbolAddress((void**)&xh,   g_xh);
    cudaGetSymbolAddress((void**)&B1,   g_B1);
    cudaGetSymbolAddress((void**)&W2h,  g_W2h);
    cudaGetSymbolAddress((void**)&H,    g_H);
    cudaGetSymbolAddress((void**)&gate, g_gate);
    cudaGetSymbolAddress((void**)&gb2,  g_gb2);
    cudaGetSymbolAddress((void**)&part, g_part);

    cudaFuncSetAttribute(moe_gemm<0>, cudaFuncAttributeMaxDynamicSharedMemorySize, SMEM_BYTES);
    cudaFuncSetAttribute(moe_gemm<1>, cudaFuncAttributeMaxDynamicSharedMemorySize, SMEM_BYTES);
    cudaFuncSetAttribute(moe_gemm<2>, cudaFuncAttributeMaxDynamicSharedMemorySize, SMEM_BYTES);
    cudaFuncSetAttribute(gate_kernel, cudaFuncAttributeMaxDynamicSharedMemorySize, DHID * NEXP * 4);

    // fp32 -> fp16 converts (weights stay in natural [K][N] layout; no transposes)
    cvt_f32_f16<<<TOKENS * DIN / 1024, 256>>>(x, xh, TOKENS * DIN);
    cvt_f32_f16<<<NEXP * DIN * DHID / 1024, 256>>>(W1, B1, NEXP * DIN * DHID);
    cvt_f32_f16<<<DIN * DHID / 1024, 256>>>(Wg1, B1 + (long long)NEXP * DIN * DHID, DIN * DHID);
    cvt_f32_f16<<<NEXP * DHID * DOUT / 1024, 256>>>(W2, W2h, NEXP * DHID * DOUT);

    // 1) gating hidden: Hg = relu(x @ Wg1 + bg1)   (slot 8)
    moe_gemm<0><<<dim3(DHID / BN, TOKENS / BM, 1), 256, SMEM_BYTES>>>(
        xh, 0, DIN,
        B1 + (long long)NEXP * DIN * DHID, 0, DHID,
        bg1, 0, nullptr,
        H + (long long)NEXP * TOKENS * DHID, 0, DHID, DIN);

    // 2) gates + gate@b2
    gate_kernel<<<TOKENS / 8, 256, DHID * NEXP * 4>>>(
        H + (long long)NEXP * TOKENS * DHID, Wg2, bg2, gate);
    gb2_kernel<<<TOKENS, 256>>>(gate, b2, gb2);

    // 3) expert layer-1 (batched over e): H[e] = gate[b,e]*relu(x @ W1[e] + b1[e])
    moe_gemm<1><<<dim3(DHID / BN, TOKENS / BM, NEXP), 256, SMEM_BYTES>>>(
        xh, 0, DIN,
        B1, (long long)DIN * DHID, DHID,
        b1, DHID, gate,
        H, (long long)TOKENS * DHID, DHID, DIN);

    // 4) layer-2 split-K over experts: part[e] = H[e] @ W2[e]
    moe_gemm<2><<<dim3(DOUT / BN, TOKENS / BM, NEXP), 256, SMEM_BYTES>>>(
        H, (long long)TOKENS * DHID, DHID,
        W2h, (long long)DHID * DOUT, DOUT,
        nullptr, 0, nullptr,
        part, (long long)TOKENS * DOUT, DOUT, DHID);

    // 5) out = gb2 + sum_e part[e]
    reduce_kernel<<<TOKENS * DOUT / 1024, 256>>>(part, gb2, (float*)d_out);
}

// round 9
// speedup vs baseline: 1.1722x; 1.0025x over previous
#include <cuda_runtime.h>
#include <cuda_fp16.h>
#include <cstdint>

#define TOKENS 4096
#define DIN    1024
#define DHID   4096
#define DOUT   1024
#define NEXP   8

// ---------------- device scratch ----------------
__device__ __half g_xh [TOKENS * DIN];                          // x fp16 [M][K]
__device__ __half g_B1 [(NEXP + 1) * (size_t)DIN * DHID];       // W1 [e][K][N] + Wg1 (e=8), fp16
__device__ __half g_W2h[(size_t)NEXP * DHID * DOUT];            // W2 flat [32768][1024] fp16
__device__ __half g_H  [(NEXP + 1) * (size_t)TOKENS * DHID];    // H[e][b][h]; slot 8 = gating hidden
__device__ float  g_gate[TOKENS * NEXP];
__device__ float  g_gb2 [TOKENS * DOUT];                        // gate @ b2
__device__ float  g_part[NEXP * (size_t)TOKENS * DOUT];         // split-K partials

// ---------------- PTX helpers ----------------
__device__ __forceinline__ void cp_async16(unsigned dst, const void* src) {
    asm volatile("cp.async.cg.shared.global [%0], [%1], 16;\n" :: "r"(dst), "l"(src));
}
__device__ __forceinline__ void cp_commit() {
    asm volatile("cp.async.commit_group;\n" ::: "memory");
}
__device__ __forceinline__ void cp_wait0() {
    asm volatile("cp.async.wait_group 0;\n" ::: "memory");
}
__device__ __forceinline__ void ldsm_x4(uint32_t* r, unsigned addr) {
    asm volatile("ldmatrix.sync.aligned.m8n8.x4.shared.b16 {%0,%1,%2,%3}, [%4];\n"
                 : "=r"(r[0]), "=r"(r[1]), "=r"(r[2]), "=r"(r[3]) : "r"(addr));
}
__device__ __forceinline__ void ldsm_x4_t(uint32_t* r, unsigned addr) {
    asm volatile("ldmatrix.sync.aligned.m8n8.x4.trans.shared.b16 {%0,%1,%2,%3}, [%4];\n"
                 : "=r"(r[0]), "=r"(r[1]), "=r"(r[2]), "=r"(r[3]) : "r"(addr));
}
__device__ __forceinline__ void mma16816(float* c, const uint32_t* a, uint32_t b0, uint32_t b1) {
    asm volatile("mma.sync.aligned.m16n8k16.row.col.f32.f16.f16.f32 "
                 "{%0,%1,%2,%3},{%4,%5,%6,%7},{%8,%9},{%0,%1,%2,%3};\n"
                 : "+f"(c[0]), "+f"(c[1]), "+f"(c[2]), "+f"(c[3])
                 : "r"(a[0]), "r"(a[1]), "r"(a[2]), "r"(a[3]), "r"(b0), "r"(b1));
}

// ---------------- fp32 -> fp16 convert ----------------
__global__ void cvt_f32_f16(const float* __restrict__ src, __half* __restrict__ dst, int n) {
    int i = (blockIdx.x * blockDim.x + threadIdx.x) * 4;
    if (i >= n) return;
    float4 v = *(const float4*)(src + i);
    *(__half2*)(dst + i)     = __floats2half2_rn(v.x, v.y);
    *(__half2*)(dst + i + 2) = __floats2half2_rn(v.z, v.w);
}

// ---------------- gating softmax ----------------
__global__ void __launch_bounds__(256) gate_kernel(
    const __half* __restrict__ Hg, const float* __restrict__ Wg2,
    const float* __restrict__ bg2, float* __restrict__ gate)
{
    extern __shared__ float sW[];   // [8][4096] transposed
    const int tid = threadIdx.x;
    for (int i = tid; i < DHID * NEXP; i += 256) {
        int k = i >> 3, j = i & 7;
        sW[j * DHID + k] = Wg2[i];
    }
    __syncthreads();
    const int warp = tid >> 5, lane = tid & 31;
    const int row = blockIdx.x * 8 + warp;
    const __half2* h2 = (const __half2*)(Hg + (long long)row * DHID);
    float a[NEXP];
#pragma unroll
    for (int j = 0; j < NEXP; j++) a[j] = 0.f;
    for (int k2 = lane; k2 < DHID / 2; k2 += 32) {
        float2 xv = __half22float2(h2[k2]);
#pragma unroll
        for (int j = 0; j < NEXP; j++)
            a[j] += xv.x * sW[j * DHID + 2 * k2] + xv.y * sW[j * DHID + 2 * k2 + 1];
    }
#pragma unroll
    for (int j = 0; j < NEXP; j++)
#pragma unroll
        for (int o = 16; o > 0; o >>= 1) a[j] += __shfl_xor_sync(0xffffffffu, a[j], o);
    float m = -1e30f;
#pragma unroll
    for (int j = 0; j < NEXP; j++) { a[j] += bg2[j]; m = fmaxf(m, a[j]); }
    float ex[NEXP], s = 0.f;
#pragma unroll
    for (int j = 0; j < NEXP; j++) { ex[j] = expf(a[j] - m); s += ex[j]; }
    if (lane < NEXP) gate[row * NEXP + lane] = ex[lane] / s;
}

// gb2[b][o] = sum_j gate[b][j] * b2[j][o]
__global__ void __launch_bounds__(256) gb2_kernel(
    const float* __restrict__ gate, const float* __restrict__ b2, float* __restrict__ gb2)
{
    int b = blockIdx.x;
    float g[NEXP];
#pragma unroll
    for (int j = 0; j < NEXP; j++) g[j] = gate[b * NEXP + j];
    for (int o = threadIdx.x; o < DOUT; o += 256) {
        float s = 0.f;
#pragma unroll
        for (int j = 0; j < NEXP; j++) s += g[j] * b2[j * DOUT + o];
        gb2[b * DOUT + o] = s;
    }
}

// out = gb2 + sum_e part[e]
__global__ void __launch_bounds__(256) reduce_kernel(
    const float* __restrict__ part, const float* __restrict__ gb2, float* __restrict__ out)
{
    const long long i = ((long long)blockIdx.x * 256 + threadIdx.x) * 4;
    float4 s = *(const float4*)(gb2 + i);
#pragma unroll
    for (int e = 0; e < NEXP; e++) {
        float4 p = *(const float4*)(part + (long long)e * TOKENS * DOUT + i);
        s.x += p.x; s.y += p.y; s.z += p.z; s.w += p.w;
    }
    *(float4*)(out + i) = s;
}

// ---------------- fused fp16 GEMM (2-stage double buffer, 2 CTAs/SM) ----------------
// A: [M][K] row-major fp16.  B: [K][N] row-major fp16.
// MODE 0: C = relu(A@B + bias)                -> fp16   (gating layer-1)
// MODE 1: C = gate[b,e]*relu(A@B + bias_e)    -> fp16   (expert layer-1, z=e)
// MODE 2: C = A_e@B_e                         -> fp32   (layer-2 partial, z=e, K=4096)
constexpr int BM = 128, BN = 128, BK = 64, STAGES = 2;
constexpr int ASTR = BK + 8;          // 72 halves
constexpr int BSTR = BN + 8;          // 136 halves
constexpr int A_TILE = BM * ASTR;     // halves
constexpr int B_TILE = BK * BSTR;
constexpr int SMEM_BYTES = STAGES * (A_TILE + B_TILE) * 2;   // 71,680 B -> 2 CTAs/SM

template <int MODE>
__global__ void __launch_bounds__(256, 2) moe_gemm(
    const __half* __restrict__ Abase, long long aSlab, int lda,
    const __half* __restrict__ Bbase, long long bStride, int ldb,
    const float* __restrict__ biasBase, long long biasStride,
    const float* __restrict__ gate,
    void* __restrict__ Cbase, long long cStride, int ldc,
    int K)
{
    extern __shared__ __half sm_[];
    __half* As = sm_;
    __half* Bs = sm_ + STAGES * A_TILE;

    const int tid  = threadIdx.x;
    const int lane = tid & 31;
    const int warp = tid >> 5;
    const int wm = warp >> 1, wn = warp & 1;   // 4x2 warp grid, warp tile 32x64
    const int bm0 = blockIdx.y * BM;
    const int bn0 = blockIdx.x * BN;
    const int e   = blockIdx.z;

    const __half* Amat = Abase + (MODE == 2 ? (long long)e * aSlab : 0LL);
    const __half* Bmat = Bbase + (long long)e * bStride;

    const unsigned sA0 = (unsigned)__cvta_generic_to_shared(As);
    const unsigned sB0 = (unsigned)__cvta_generic_to_shared(Bs);

    float acc[2][8][4];
#pragma unroll
    for (int a = 0; a < 2; a++)
#pragma unroll
        for (int b = 0; b < 8; b++)
#pragma unroll
            for (int c = 0; c < 4; c++) acc[a][b][c] = 0.f;

    const int KT = K / BK;

    auto load_tile = [&](int kt, int buf) {
        const int k0 = kt * BK;
        const __half* aSrc = Amat + k0;
        const __half* bSrc = Bmat + (long long)k0 * ldb + bn0;
        const unsigned da = sA0 + buf * (A_TILE * 2);
        const unsigned db = sB0 + buf * (B_TILE * 2);
#pragma unroll
        for (int i = 0; i < 4; i++) {
            int c = tid + i * 256;
            int r = c >> 3, c8 = (c & 7) << 3;
            cp_async16(da + (unsigned)(r * ASTR + c8) * 2,
                       aSrc + (long long)(bm0 + r) * lda + c8);
        }
#pragma unroll
        for (int i = 0; i < 4; i++) {
            int c = tid + i * 256;
            int r = c >> 4, c16 = (c & 15) << 3;
            cp_async16(db + (unsigned)(r * BSTR + c16) * 2,
                       bSrc + (long long)r * ldb + c16);
        }
        cp_commit();
    };

    load_tile(0, 0);

    const int lr = lane & 15;
    const int lc = (lane >> 4) << 3;

    for (int kt = 0; kt < KT; kt++) {
        cp_wait0();
        __syncthreads();
        const int nt = kt + 1;
        if (nt < KT) load_tile(nt, nt & 1);    // in flight during compute(kt)

        const int buf = kt & 1;
        const unsigned aB = sA0 + buf * (A_TILE * 2);
        const unsigned bB = sB0 + buf * (B_TILE * 2);
#pragma unroll
        for (int ks = 0; ks < BK / 16; ks++) {
            uint32_t af[2][4];
#pragma unroll
            for (int mb = 0; mb < 2; mb++)
                ldsm_x4(af[mb], aB + (unsigned)((wm * 32 + mb * 16 + lr) * ASTR + ks * 16 + lc) * 2);
            uint32_t bf[4][4];
#pragma unroll
            for (int nb = 0; nb < 4; nb++)
                ldsm_x4_t(bf[nb], bB + (unsigned)((ks * 16 + lr) * BSTR + wn * 64 + nb * 16 + lc) * 2);
#pragma unroll
            for (int mb = 0; mb < 2; mb++)
#pragma unroll
                for (int nb = 0; nb < 4; nb++) {
                    mma16816(acc[mb][2 * nb],     af[mb], bf[nb][0], bf[nb][1]);
                    mma16816(acc[mb][2 * nb + 1], af[mb], bf[nb][2], bf[nb][3]);
                }
        }
    }

    // -------- epilogue --------
    const int g  = lane >> 2;
    const int tg = lane & 3;

    if constexpr (MODE == 0 || MODE == 1) {
        __half* C = (__half*)Cbase + (long long)e * cStride;
        const float* bias = biasBase + (long long)e * biasStride;
#pragma unroll
        for (int mb = 0; mb < 2; mb++)
#pragma unroll
            for (int i = 0; i < 2; i++) {
                const int row = bm0 + wm * 32 + mb * 16 + g + i * 8;
                float gv = 1.f;
                if constexpr (MODE == 1) gv = gate[row * NEXP + e];
#pragma unroll
                for (int nb = 0; nb < 8; nb++) {
                    const int col = bn0 + wn * 64 + nb * 8 + tg * 2;
                    float v0 = fmaxf(acc[mb][nb][2 * i + 0] + bias[col],     0.f) * gv;
                    float v1 = fmaxf(acc[mb][nb][2 * i + 1] + bias[col + 1], 0.f) * gv;
                    *(__half2*)(C + (long long)row * ldc + col) = __floats2half2_rn(v0, v1);
                }
            }
    } else {
        float* C = (float*)Cbase + (long long)e * cStride;
#pragma unroll
        for (int mb = 0; mb < 2; mb++)
#pragma unroll
            for (int i = 0; i < 2; i++) {
                const int row = bm0 + wm * 32 + mb * 16 + g + i * 8;
#pragma unroll
                for (int nb = 0; nb < 8; nb++) {
                    const int col = bn0 + wn * 64 + nb * 8 + tg * 2;
                    float2 o;
                    o.x = acc[mb][nb][2 * i + 0];
                    o.y = acc[mb][nb][2 * i + 1];
                    *(float2*)(C + (long long)row * ldc + col) = o;
                }
            }
    }
}

// ---------------- launch ----------------
extern "C" void kernel_launch(void* const* d_in, const int* in_sizes, int n_in,
                              void* d_out, int out_size)
{
    const float* x   = (const float*)d_in[0];
    const float* W1  = (const float*)d_in[1];
    const float* b1  = (const float*)d_in[2];
    const float* W2  = (const float*)d_in[3];
    const float* b2  = (const float*)d_in[4];
    const float* Wg1 = (const float*)d_in[5];
    const float* bg1 = (const float*)d_in[6];
    const float* Wg2 = (const float*)d_in[7];
    const float* bg2 = (const float*)d_in[8];

    __half *xh, *B1, *W2h, *H;
    float *gate, *gb2, *part;
    cudaGetSymbolAddress((void**)&xh,   g_xh);
    cudaGetSymbolAddress((void**)&B1,   g_B1);
    cudaGetSymbolAddress((void**)&W2h,  g_W2h);
    cudaGetSymbolAddress((void**)&H,    g_H);
    cudaGetSymbolAddress((void**)&gate, g_gate);
    cudaGetSymbolAddress((void**)&gb2,  g_gb2);
    cudaGetSymbolAddress((void**)&part, g_part);

    cudaFuncSetAttribute(moe_gemm<0>, cudaFuncAttributeMaxDynamicSharedMemorySize, SMEM_BYTES);
    cudaFuncSetAttribute(moe_gemm<1>, cudaFuncAttributeMaxDynamicSharedMemorySize, SMEM_BYTES);
    cudaFuncSetAttribute(moe_gemm<2>, cudaFuncAttributeMaxDynamicSharedMemorySize, SMEM_BYTES);
    cudaFuncSetAttribute(gate_kernel, cudaFuncAttributeMaxDynamicSharedMemorySize, DHID * NEXP * 4);

    // fp32 -> fp16 converts (weights stay in natural [K][N] layout)
    cvt_f32_f16<<<TOKENS * DIN / 1024, 256>>>(x, xh, TOKENS * DIN);
    cvt_f32_f16<<<NEXP * DIN * DHID / 1024, 256>>>(W1, B1, NEXP * DIN * DHID);
    cvt_f32_f16<<<DIN * DHID / 1024, 256>>>(Wg1, B1 + (long long)NEXP * DIN * DHID, DIN * DHID);
    cvt_f32_f16<<<NEXP * DHID * DOUT / 1024, 256>>>(W2, W2h, NEXP * DHID * DOUT);

    // 1) gating hidden: Hg = relu(x @ Wg1 + bg1)   (slot 8)
    moe_gemm<0><<<dim3(DHID / BN, TOKENS / BM, 1), 256, SMEM_BYTES>>>(
        xh, 0, DIN,
        B1 + (long long)NEXP * DIN * DHID, 0, DHID,
        bg1, 0, nullptr,
        H + (long long)NEXP * TOKENS * DHID, 0, DHID, DIN);

    // 2) gates + gate@b2
    gate_kernel<<<TOKENS / 8, 256, DHID * NEXP * 4>>>(
        H + (long long)NEXP * TOKENS * DHID, Wg2, bg2, gate);
    gb2_kernel<<<TOKENS, 256>>>(gate, b2, gb2);

    // 3) expert layer-1 (batched over e): H[e] = gate[b,e]*relu(x @ W1[e] + b1[e])
    moe_gemm<1><<<dim3(DHID / BN, TOKENS / BM, NEXP), 256, SMEM_BYTES>>>(
        xh, 0, DIN,
        B1, (long long)DIN * DHID, DHID,
        b1, DHID, gate,
        H, (long long)TOKENS * DHID, DHID, DIN);

    // 4) layer-2 split-K over experts: part[e] = H[e] @ W2[e]
    moe_gemm<2><<<dim3(DOUT / BN, TOKENS / BM, NEXP), 256, SMEM_BYTES>>>(
        H, (long long)TOKENS * DHID, DHID,
        W2h, (long long)DHID * DOUT, DOUT,
        nullptr, 0, nullptr,
        part, (long long)TOKENS * DOUT, DOUT, DHID);

    // 5) out = gb2 + sum_e part[e]
    reduce_kernel<<<TOKENS * DOUT / 1024, 256>>>(part, gb2, (float*)d_out);
}